// round 5
// baseline (speedup 1.0000x reference)
#include <cuda_runtime.h>
#include <math.h>
#include <stdint.h>

#define B_    256
#define T_    100
#define IN_   784
#define H_    200
#define R_    4
#define N_    128
#define D_    40
#define NCLS  5
#define G4H   800
#define RD    160
#define MSTRIDE 41

#define BPB   2
#define NBLK  (B_/BPB)
#define THREADS 512

// ---------------- device scratch ----------------
__device__ float g_G[B_*T_*G4H];        // x@Wih.T + bih
__device__ float g_Wg4[H_*H_*4];        // [k=200][i=200][g=4]  gate-interleaved Whh
__device__ float g_Wka2[H_*RD*2];       // [k=200][j=160][key,add]
__device__ float g_WrhT[RD*H_];         // [k=160][j=200]

// ---------------- weight repack ----------------
__global__ void prep_weights(const float* __restrict__ Whh,
                             const float* __restrict__ Wkey,
                             const float* __restrict__ Wadd,
                             const float* __restrict__ Wrh) {
    int i = blockIdx.x * 256 + threadIdx.x;
    if (i < 160000) {                       // Wg4[(k*200+ii)*4+g] = Whh[g*200+ii][k]
        int k = i / 800, rem = i % 800, ii = rem >> 2, g = rem & 3;
        g_Wg4[i] = Whh[(g * 200 + ii) * 200 + k];
    } else if (i < 224000) {                // Wka2[(k*160+j)*2+w]
        int z = i - 160000;
        int k = z / 320, rem = z % 320, j = rem >> 1, w = rem & 1;
        g_Wka2[z] = w ? Wadd[j * 200 + k] : Wkey[j * 200 + k];
    } else if (i < 256000) {                // WrhT[k][j] = Wrh[j][k]
        int z = i - 224000; int k = z / 200, j = z % 200;
        g_WrhT[z] = Wrh[j * 160 + k];
    }
}

// ---------------- big input GEMM (R3 scalar-FFMA version): G = x @ Wih^T + bih ----------------
#define GBM 128
#define GBN 128
#define GBK 16
__global__ __launch_bounds__(256) void gemm_gates_x(
    const float* __restrict__ X, const float* __restrict__ Wih,
    const float* __restrict__ bih) {
    __shared__ float As[GBK][GBM + 4];
    __shared__ float Bs[GBK][GBN + 4];
    const int tid = threadIdx.x;
    const int m0 = blockIdx.y * GBM;
    const int n0 = blockIdx.x * GBN;
    const int tx = tid & 15, ty = tid >> 4;

    float acc[8][8];
#pragma unroll
    for (int i = 0; i < 8; i++)
#pragma unroll
        for (int j = 0; j < 8; j++) acc[i][j] = 0.f;

    const int ar = tid >> 1, ac = (tid & 1) * 8;
    const int bn = n0 + ar;

    for (int kt = 0; kt < IN_; kt += GBK) {
        {
            const float* src = X + (size_t)(m0 + ar) * IN_ + kt + ac;
            float4 v0 = *(const float4*)src;
            float4 v1 = *(const float4*)(src + 4);
            As[ac + 0][ar] = v0.x; As[ac + 1][ar] = v0.y;
            As[ac + 2][ar] = v0.z; As[ac + 3][ar] = v0.w;
            As[ac + 4][ar] = v1.x; As[ac + 5][ar] = v1.y;
            As[ac + 6][ar] = v1.z; As[ac + 7][ar] = v1.w;
        }
        {
            float4 v0 = make_float4(0.f,0.f,0.f,0.f), v1 = v0;
            if (bn < G4H) {
                const float* src = Wih + (size_t)bn * IN_ + kt + ac;
                v0 = *(const float4*)src;
                v1 = *(const float4*)(src + 4);
            }
            Bs[ac + 0][ar] = v0.x; Bs[ac + 1][ar] = v0.y;
            Bs[ac + 2][ar] = v0.z; Bs[ac + 3][ar] = v0.w;
            Bs[ac + 4][ar] = v1.x; Bs[ac + 5][ar] = v1.y;
            Bs[ac + 6][ar] = v1.z; Bs[ac + 7][ar] = v1.w;
        }
        __syncthreads();
#pragma unroll
        for (int k = 0; k < GBK; k++) {
            float ra[8], rb[8];
#pragma unroll
            for (int i = 0; i < 8; i++) ra[i] = As[k][ty + 16 * i];
#pragma unroll
            for (int j = 0; j < 8; j++) rb[j] = Bs[k][tx + 16 * j];
#pragma unroll
            for (int i = 0; i < 8; i++)
#pragma unroll
                for (int j = 0; j < 8; j++) acc[i][j] += ra[i] * rb[j];
        }
        __syncthreads();
    }
    float bihr[8];
#pragma unroll
    for (int j = 0; j < 8; j++) {
        int gn = n0 + tx + 16 * j;
        bihr[j] = (gn < G4H) ? bih[gn] : 0.f;
    }
#pragma unroll
    for (int i = 0; i < 8; i++) {
        size_t base = (size_t)(m0 + ty + 16 * i) * G4H;
#pragma unroll
        for (int j = 0; j < 8; j++) {
            int gn = n0 + tx + 16 * j;
            if (gn < G4H) g_G[base + gn] = acc[i][j] + bihr[j];
        }
    }
}

// ---------------- recurrent kernel (R4 version, validated correct) ----------------
struct __align__(16) BS {
    float M[N_ * MSTRIDE];   // 5248
    float h[H_];             // 200 (post-LSTM h_t)
    float hpre[H_];          // 200 (h after +r@Wrh)
    float c[H_];             // 200
    float r[RD];             // 160
    float key[RD];           // 160
    float add[RD];           // 160
    float wr[R_ * N_];       // 512
    float wu[N_];            // 128
    float wwsum[N_];         // 128
    float Ksm[R_ * N_];      // 512
    float m2[N_];            // 128
    float wlu[N_];           // 128
    float outh[NCLS];        // 5
    float key2[R_];          // 4
    float sig;               // 1
    float pad_[2];           // -> 7876 floats = 31504 B (mult of 16)
};
#define BSF (sizeof(BS)/4)

__device__ __forceinline__ float sigmoidf_(float x) { return 1.f / (1.f + expf(-x)); }

__global__ __launch_bounds__(THREADS) void mann_recurrent(
    const float* __restrict__ bkey, const float* __restrict__ badd,
    const float* __restrict__ Wsig, const float* __restrict__ bsig,
    const float* __restrict__ Who,  const float* __restrict__ bho,
    const float* __restrict__ Wro,  const float* __restrict__ bro,
    const float* __restrict__ brh,  const float* __restrict__ bhh,
    float* __restrict__ out) {
    extern __shared__ float smemf[];
    BS* S = reinterpret_cast<BS*>(smemf);
    float* sWrh = smemf + 2 * BSF;   // 32000 floats: WrhT pinned in SMEM

    const int tid = threadIdx.x;
    const int blk = blockIdx.x;
    const int wid = tid >> 5, lane = tid & 31;

    for (int b = 0; b < BPB; b++) {
        BS& s = S[b];
        for (int i = tid; i < N_ * MSTRIDE; i += THREADS) s.M[i] = 0.f;
        for (int i = tid; i < H_; i += THREADS) { s.h[i] = 0.f; s.c[i] = 0.f; }
        for (int i = tid; i < RD; i += THREADS) s.r[i] = 0.f;
        for (int i = tid; i < R_ * N_; i += THREADS) s.wr[i] = 0.f;
        for (int i = tid; i < N_; i += THREADS) s.wu[i] = 0.f;
    }
    for (int i = tid; i < RD * H_; i += THREADS) sWrh[i] = g_WrhT[i];
    __syncthreads();

    const int p_b = (tid < 400) ? tid / 200 : 0;
    const int p_i = (tid < 400) ? tid % 200 : 0;

    for (int t = 0; t < T_; t++) {
        // ---- prefetch this step's G row into registers ----
        float gin0 = 0.f, gin1 = 0.f, gin2 = 0.f, gin3 = 0.f;
        if (tid < 400) {
            const float* Gp = g_G + ((size_t)(blk * BPB + p_b) * T_ + t) * G4H + p_i;
            gin0 = Gp[0]; gin1 = Gp[200]; gin2 = Gp[400]; gin3 = Gp[600];
        }

        // ---- phase 1: hpre = h + r@WrhT + brh | LRU select | prev-step output ----
        if (tid < 400) {
            const float* rr = S[p_b].r;
            float acc = 0.f;
#pragma unroll 8
            for (int k = 0; k < RD; k++) acc += rr[k] * sWrh[k * 200 + p_i];
            S[p_b].hpre[p_i] = S[p_b].h[p_i] + acc + brh[p_i];
        } else if (wid == 13 || wid == 14) {
            int b = wid - 13;
            unsigned long long kv[4];
            float wl[4];
#pragma unroll
            for (int q = 0; q < 4; q++) {
                int n = lane + 32 * q;
                unsigned u = __float_as_uint(S[b].wu[n]);
                u = (u & 0x80000000u) ? ~u : (u | 0x80000000u);
                kv[q] = ((unsigned long long)u << 32) | (unsigned)n;
                wl[q] = 0.f;
            }
#pragma unroll
            for (int ss = 0; ss < 4; ss++) {
                unsigned long long m = kv[0]; int qi = 0;
#pragma unroll
                for (int q = 1; q < 4; q++) if (kv[q] < m) { m = kv[q]; qi = q; }
                unsigned long long wm = m;
#pragma unroll
                for (int o = 16; o > 0; o >>= 1) {
                    unsigned long long x = __shfl_xor_sync(0xffffffffu, wm, o);
                    if (x < wm) wm = x;
                }
                if (m == wm) { wl[qi] = 1.f; kv[qi] = ~0ull; }
            }
#pragma unroll
            for (int q = 0; q < 4; q++) S[b].wlu[lane + 32 * q] = wl[q];
        } else if (wid == 15 && t > 0) {
            for (int p = 0; p < BPB * NCLS; p++) {
                int b = p / NCLS, cls = p % NCLS;
                const float* rr = S[b].r;
                float acc = 0.f;
#pragma unroll
                for (int k = lane; k < RD; k += 32) acc += rr[k] * Wro[cls * RD + k];
#pragma unroll
                for (int o = 16; o > 0; o >>= 1) acc += __shfl_down_sync(0xffffffffu, acc, o);
                if (lane == 0)
                    out[((size_t)(blk * BPB + b) * T_ + (t - 1)) * NCLS + cls] = acc + S[b].outh[cls];
            }
        }
        __syncthreads();

        // ---- phase 2: gates GEMV (gate-interleaved) + LSTM pointwise, fused ----
        if (tid < 400) {
            float a0 = 0.f, a1 = 0.f, a2 = 0.f, a3 = 0.f;
            const float4* W = reinterpret_cast<const float4*>(g_Wg4) + p_i;
            const float* hp = S[p_b].hpre;
#pragma unroll 10
            for (int k = 0; k < H_; k++) {
                float4 w = W[k * 200];
                float hk = hp[k];
                a0 += w.x * hk; a1 += w.y * hk; a2 += w.z * hk; a3 += w.w * hk;
            }
            a0 += gin0 + bhh[p_i];
            a1 += gin1 + bhh[200 + p_i];
            a2 += gin2 + bhh[400 + p_i];
            a3 += gin3 + bhh[600 + p_i];
            float ig = sigmoidf_(a0), fg = sigmoidf_(a1);
            float gg = tanhf(a2),    og = sigmoidf_(a3);
            float ct = fg * S[p_b].c[p_i] + ig * gg;
            S[p_b].c[p_i] = ct;
            S[p_b].h[p_i] = og * tanhf(ct);
        }
        __syncthreads();

        // ---- phase 4: key/add GEMV (pair-interleaved) | sigma | outh ----
        if (tid < 320) {
            int b = tid / 160, j = tid % 160;
            float kk = 0.f, aa = 0.f;
            const float2* W = reinterpret_cast<const float2*>(g_Wka2) + j;
            const float* hh = S[b].h;
#pragma unroll 10
            for (int k = 0; k < H_; k++) {
                float2 w = W[k * 160];
                float hk = hh[k];
                kk += w.x * hk; aa += w.y * hk;
            }
            S[b].key[j] = kk + bkey[j];
            S[b].add[j] = aa + badd[j];
        } else if (wid == 10 || wid == 11) {
            int b = wid - 10;
            float p = 0.f;
            for (int k = lane; k < H_; k += 32) p += S[b].h[k] * Wsig[k];
#pragma unroll
            for (int o = 16; o > 0; o >>= 1) p += __shfl_xor_sync(0xffffffffu, p, o);
            if (lane == 0) S[b].sig = p + bsig[0];
        } else if (wid == 12 || wid == 13) {
            int b = wid - 12;
            const float* hh = S[b].h;
            for (int cls = 0; cls < NCLS; cls++) {
                float acc = 0.f;
#pragma unroll
                for (int k = lane; k < H_; k += 32) acc += hh[k] * Who[cls * H_ + k];
#pragma unroll
                for (int o = 16; o > 0; o >>= 1) acc += __shfl_down_sync(0xffffffffu, acc, o);
                if (lane == 0) S[b].outh[cls] = acc + bho[cls] + bro[cls];
            }
        }
        __syncthreads();

        // ---- phase 6: M update + wwsum + m2 ; key2 ----
        {
            int b = tid >> 8;
            int n = (tid >> 1) & 127;
            int dh = tid & 1;
            BS& s = S[b];
            float sg = s.sig, omsg = 1.f - sg;
            float wl = s.wlu[n];
            float w0 = sg * s.wr[n]       + omsg * wl;
            float w1 = sg * s.wr[128 + n] + omsg * wl;
            float w2 = sg * s.wr[256 + n] + omsg * wl;
            float w3 = sg * s.wr[384 + n] + omsg * wl;
            if (dh == 0) s.wwsum[n] = w0 + w1 + w2 + w3;
            float m2p = 0.f;
            int d0 = dh * 20;
#pragma unroll
            for (int dd = 0; dd < 20; dd++) {
                int d = d0 + dd;
                float mv = s.M[n * MSTRIDE + d] * wl
                         + w0 * s.add[d] + w1 * s.add[40 + d]
                         + w2 * s.add[80 + d] + w3 * s.add[120 + d];
                s.M[n * MSTRIDE + d] = mv;
                m2p += mv * mv;
            }
            m2p += __shfl_xor_sync(0xffffffffu, m2p, 1);
            if (dh == 0) s.m2[n] = m2p;
        }
        if (tid < 8) {
            int b = tid >> 2, r = tid & 3;
            float sum = 0.f;
#pragma unroll
            for (int d = 0; d < D_; d++) { float v = S[b].key[r * 40 + d]; sum += v * v; }
            S[b].key2[r] = sum;
        }
        __syncthreads();

        // ---- phase 7: cosine similarity ----
        for (int e = tid; e < 1024; e += THREADS) {
            int b = e >> 9, rn = e & 511, r = rn >> 7, n = rn & 127;
            BS& s = S[b];
            const float* kp = s.key + r * 40;
            const float* mp = s.M + n * MSTRIDE;
            float dot = 0.f;
#pragma unroll
            for (int d = 0; d < D_; d++) dot += kp[d] * mp[d];
            s.Ksm[rn] = dot / sqrtf(s.key2[r] * s.m2[n] + 1e-6f);
        }
        __syncthreads();

        // ---- phase 8: softmax over n (warp per (b,r)) ----
        if (wid < 8) {
            int b = wid >> 2, r = wid & 3;
            BS& s = S[b];
            float v0 = s.Ksm[r * N_ + lane];
            float v1 = s.Ksm[r * N_ + 32 + lane];
            float v2 = s.Ksm[r * N_ + 64 + lane];
            float v3 = s.Ksm[r * N_ + 96 + lane];
            float mx = fmaxf(fmaxf(v0, v1), fmaxf(v2, v3));
#pragma unroll
            for (int o = 16; o > 0; o >>= 1) mx = fmaxf(mx, __shfl_xor_sync(0xffffffffu, mx, o));
            float e0 = expf(v0 - mx), e1 = expf(v1 - mx), e2 = expf(v2 - mx), e3 = expf(v3 - mx);
            float su = e0 + e1 + e2 + e3;
#pragma unroll
            for (int o = 16; o > 0; o >>= 1) su += __shfl_xor_sync(0xffffffffu, su, o);
            float inv = 1.f / su;
            s.wr[r * N_ + lane]      = e0 * inv;
            s.wr[r * N_ + 32 + lane] = e1 * inv;
            s.wr[r * N_ + 64 + lane] = e2 * inv;
            s.wr[r * N_ + 96 + lane] = e3 * inv;
        }
        __syncthreads();

        // ---- phase 9+10: wu update ; r_t = wr @ M ----
        if (tid < 256) {
            int b = tid >> 7, n = tid & 127;
            BS& s = S[b];
            s.wu[n] = 0.95f * s.wu[n]
                    + (s.wr[n] + s.wr[128 + n] + s.wr[256 + n] + s.wr[384 + n])
                    + s.wwsum[n];
        }
        if (tid < 320) {
            int b = tid / 160, rd = tid % 160;
            int r = rd / 40, d = rd % 40;
            BS& s = S[b];
            const float* wrp = s.wr + r * N_;
            float dot = 0.f;
#pragma unroll 8
            for (int n = 0; n < N_; n++) dot += wrp[n] * s.M[n * MSTRIDE + d];
            s.r[rd] = dot;
        }
        __syncthreads();
    }

    // ---- final output (t = 99) ----
    if (wid == 15) {
        for (int p = 0; p < BPB * NCLS; p++) {
            int b = p / NCLS, cls = p % NCLS;
            const float* rr = S[b].r;
            float acc = 0.f;
#pragma unroll
            for (int k = lane; k < RD; k += 32) acc += rr[k] * Wro[cls * RD + k];
#pragma unroll
            for (int o = 16; o > 0; o >>= 1) acc += __shfl_down_sync(0xffffffffu, acc, o);
            if (lane == 0)
                out[((size_t)(blk * BPB + b) * T_ + (T_ - 1)) * NCLS + cls] = acc + S[b].outh[cls];
        }
    }
}

// ---------------- launch ----------------
extern "C" void kernel_launch(void* const* d_in, const int* in_sizes, int n_in,
                              void* d_out, int out_size) {
    const float* x    = (const float*)d_in[0];
    const float* Wkey = (const float*)d_in[1];
    const float* bkey = (const float*)d_in[2];
    const float* Wadd = (const float*)d_in[3];
    const float* badd = (const float*)d_in[4];
    const float* Wsig = (const float*)d_in[5];
    const float* bsig = (const float*)d_in[6];
    const float* Who  = (const float*)d_in[7];
    const float* bho  = (const float*)d_in[8];
    const float* Wro  = (const float*)d_in[9];
    const float* bro  = (const float*)d_in[10];
    const float* Wrh  = (const float*)d_in[11];
    const float* brh  = (const float*)d_in[12];
    const float* Wih  = (const float*)d_in[13];
    const float* bih  = (const float*)d_in[14];
    const float* Whh  = (const float*)d_in[15];
    const float* bhh  = (const float*)d_in[16];
    float* out = (float*)d_out;

    prep_weights<<<1000, 256>>>(Whh, Wkey, Wadd, Wrh);
    gemm_gates_x<<<dim3((G4H + GBN - 1) / GBN, B_ * T_ / GBM), 256>>>(x, Wih, bih);

    size_t shmem = 2 * sizeof(BS) + (size_t)RD * H_ * 4;
    cudaFuncSetAttribute(mann_recurrent, cudaFuncAttributeMaxDynamicSharedMemorySize, (int)shmem);
    mann_recurrent<<<NBLK, THREADS, shmem>>>(bkey, badd, Wsig, bsig, Who, bho,
                                             Wro, bro, brh, bhh, out);
}

// round 6
// speedup vs baseline: 2.1376x; 2.1376x over previous
#include <cuda_runtime.h>
#include <math.h>
#include <stdint.h>

#define B_    256
#define T_    100
#define IN_   784
#define H_    200
#define R_    4
#define N_    128
#define D_    40
#define NCLS  5
#define G4H   800
#define RD    160
#define MSTRIDE 41
#define RSTR  164      // rAll stride (banks: 164%32=4 -> 8 distinct banks for b=0..7)

#define BPB   2
#define NBLK  (B_/BPB)
#define THREADS 512
#define CS    4        // cluster size (CTAs); cluster covers 8 batch elements

// ---------------- device scratch ----------------
__device__ float g_G[B_*T_*G4H];        // x@Wih.T + bih
__device__ float g_Wg4[H_*H_*4];        // [k=200][i=200][g=4]  gate-interleaved Whh
__device__ float g_Wka2[H_*RD*2];       // [k=200][j=160][key,add]
__device__ float g_WrhT[RD*H_];         // [k=160][j=200]

// ---------------- cluster helpers ----------------
__device__ __forceinline__ unsigned ctarank() {
    unsigned r; asm("mov.u32 %0, %%cluster_ctarank;" : "=r"(r)); return r;
}
__device__ __forceinline__ void bcast_all(void* p, float v) {
    unsigned a = (unsigned)__cvta_generic_to_shared(p);
#pragma unroll
    for (int r = 0; r < CS; r++) {
        unsigned ra;
        asm("mapa.shared::cluster.u32 %0, %1, %2;" : "=r"(ra) : "r"(a), "r"(r));
        asm volatile("st.shared::cluster.f32 [%0], %1;" :: "r"(ra), "f"(v));
    }
}
__device__ __forceinline__ void st_rank(void* p, float v, int r) {
    unsigned a = (unsigned)__cvta_generic_to_shared(p);
    unsigned ra;
    asm("mapa.shared::cluster.u32 %0, %1, %2;" : "=r"(ra) : "r"(a), "r"(r));
    asm volatile("st.shared::cluster.f32 [%0], %1;" :: "r"(ra), "f"(v));
}
#define CLUSTER_SYNC() do { \
    asm volatile("barrier.cluster.arrive.aligned;" ::: "memory"); \
    asm volatile("barrier.cluster.wait.aligned;"   ::: "memory"); \
} while (0)

// ---------------- weight repack ----------------
__global__ void prep_weights(const float* __restrict__ Whh,
                             const float* __restrict__ Wkey,
                             const float* __restrict__ Wadd,
                             const float* __restrict__ Wrh) {
    int i = blockIdx.x * 256 + threadIdx.x;
    if (i < 160000) {
        int k = i / 800, rem = i % 800, ii = rem >> 2, g = rem & 3;
        g_Wg4[i] = Whh[(g * 200 + ii) * 200 + k];
    } else if (i < 224000) {
        int z = i - 160000;
        int k = z / 320, rem = z % 320, j = rem >> 1, w = rem & 1;
        g_Wka2[z] = w ? Wadd[j * 200 + k] : Wkey[j * 200 + k];
    } else if (i < 256000) {
        int z = i - 224000; int k = z / 200, j = z % 200;
        g_WrhT[z] = Wrh[j * 160 + k];
    }
}

// ---------------- big input GEMM (R3 version, known-good): G = x @ Wih^T + bih ----------------
#define GBM 128
#define GBN 128
#define GBK 16
__global__ __launch_bounds__(256) void gemm_gates_x(
    const float* __restrict__ X, const float* __restrict__ Wih,
    const float* __restrict__ bih) {
    __shared__ float As[GBK][GBM + 4];
    __shared__ float Bs[GBK][GBN + 4];
    const int tid = threadIdx.x;
    const int m0 = blockIdx.y * GBM;
    const int n0 = blockIdx.x * GBN;
    const int tx = tid & 15, ty = tid >> 4;

    float acc[8][8];
#pragma unroll
    for (int i = 0; i < 8; i++)
#pragma unroll
        for (int j = 0; j < 8; j++) acc[i][j] = 0.f;

    const int ar = tid >> 1, ac = (tid & 1) * 8;
    const int bn = n0 + ar;

    for (int kt = 0; kt < IN_; kt += GBK) {
        {
            const float* src = X + (size_t)(m0 + ar) * IN_ + kt + ac;
            float4 v0 = *(const float4*)src;
            float4 v1 = *(const float4*)(src + 4);
            As[ac + 0][ar] = v0.x; As[ac + 1][ar] = v0.y;
            As[ac + 2][ar] = v0.z; As[ac + 3][ar] = v0.w;
            As[ac + 4][ar] = v1.x; As[ac + 5][ar] = v1.y;
            As[ac + 6][ar] = v1.z; As[ac + 7][ar] = v1.w;
        }
        {
            float4 v0 = make_float4(0.f,0.f,0.f,0.f), v1 = v0;
            if (bn < G4H) {
                const float* src = Wih + (size_t)bn * IN_ + kt + ac;
                v0 = *(const float4*)src;
                v1 = *(const float4*)(src + 4);
            }
            Bs[ac + 0][ar] = v0.x; Bs[ac + 1][ar] = v0.y;
            Bs[ac + 2][ar] = v0.z; Bs[ac + 3][ar] = v0.w;
            Bs[ac + 4][ar] = v1.x; Bs[ac + 5][ar] = v1.y;
            Bs[ac + 6][ar] = v1.z; Bs[ac + 7][ar] = v1.w;
        }
        __syncthreads();
#pragma unroll
        for (int k = 0; k < GBK; k++) {
            float ra[8], rb[8];
#pragma unroll
            for (int i = 0; i < 8; i++) ra[i] = As[k][ty + 16 * i];
#pragma unroll
            for (int j = 0; j < 8; j++) rb[j] = Bs[k][tx + 16 * j];
#pragma unroll
            for (int i = 0; i < 8; i++)
#pragma unroll
                for (int j = 0; j < 8; j++) acc[i][j] += ra[i] * rb[j];
        }
        __syncthreads();
    }
    float bihr[8];
#pragma unroll
    for (int j = 0; j < 8; j++) {
        int gn = n0 + tx + 16 * j;
        bihr[j] = (gn < G4H) ? bih[gn] : 0.f;
    }
#pragma unroll
    for (int i = 0; i < 8; i++) {
        size_t base = (size_t)(m0 + ty + 16 * i) * G4H;
#pragma unroll
        for (int j = 0; j < 8; j++) {
            int gn = n0 + tx + 16 * j;
            if (gn < G4H) g_G[base + gn] = acc[i][j] + bihr[j];
        }
    }
}

// ---------------- recurrent kernel (clustered) ----------------
// Owner-local state (2 batch elements per CTA). h lives in htAll (cluster-replicated).
struct __align__(16) BS {
    float M[N_ * MSTRIDE];   // 5248
    float r[RD];             // 160
    float key[RD];           // 160
    float add[RD];           // 160
    float wr[R_ * N_];       // 512
    float wu[N_];            // 128
    float wwsum[N_];         // 128
    float Ksm[R_ * N_];      // 512
    float m2[N_];            // 128
    float wlu[N_];           // 128
    float outh[NCLS];        // 5
    float key2[R_];          // 4
    float sig;               // 1
    float pad_[2];           // 7276 floats = 29104 B (mult of 16)
};
#define BSF (sizeof(BS)/4)

// SMEM layout (floats)
#define OFF_SWRH   (2*BSF)             // 160*50 = 8000  (my Wrh column slice [k][i])
#define OFF_HPRE   (OFF_SWRH + 8000)   // 8*200 = 1600
#define OFF_HT     (OFF_HPRE + 1600)   // 8*200 = 1600
#define OFF_RALL   (OFF_HT   + 1600)   // 8*164 = 1312
#define OFF_CSL    (OFF_RALL + 1312)   // 8*50  = 400
#define OFF_PBUF   (OFF_CSL  + 400)    // 400*32 = 12800
#define SMEM_FLOATS (OFF_PBUF + 12800)

__device__ __forceinline__ float sigmoidf_(float x) { return 1.f / (1.f + expf(-x)); }

__global__ __launch_bounds__(THREADS) __cluster_dims__(CS, 1, 1)
void mann_recurrent(
    const float* __restrict__ bkey, const float* __restrict__ badd,
    const float* __restrict__ Wsig, const float* __restrict__ bsig,
    const float* __restrict__ Who,  const float* __restrict__ bho,
    const float* __restrict__ Wro,  const float* __restrict__ bro,
    const float* __restrict__ brh,  const float* __restrict__ bhh,
    float* __restrict__ out) {
    extern __shared__ float smemf[];
    BS* S          = reinterpret_cast<BS*>(smemf);
    float* sWrh    = smemf + OFF_SWRH;   // [k=160][i=50]
    float* hpreAll = smemf + OFF_HPRE;   // [b=8][200]
    float* htAll   = smemf + OFF_HT;     // [b=8][200]
    float* rAll    = smemf + OFF_RALL;   // [b=8][RSTR]
    float* cSlice  = smemf + OFF_CSL;    // [b=8][50]
    float* Pbuf    = smemf + OFF_PBUF;   // partials

    const int tid  = threadIdx.x;
    const int blk  = blockIdx.x;
    const int wid  = tid >> 5, lane = tid & 31;
    const unsigned rank = ctarank();
    const int bbase = (blk >> 2) * 8;    // cluster's first global batch index

    // ---------------- init ----------------
    for (int b = 0; b < BPB; b++) {
        BS& s = S[b];
        for (int i = tid; i < N_ * MSTRIDE; i += THREADS) s.M[i] = 0.f;
        for (int i = tid; i < RD; i += THREADS) s.r[i] = 0.f;
        for (int i = tid; i < R_ * N_; i += THREADS) s.wr[i] = 0.f;
        for (int i = tid; i < N_; i += THREADS) s.wu[i] = 0.f;
    }
    for (int i = tid; i < 8 * 200; i += THREADS) htAll[i] = 0.f;
    for (int i = tid; i < 8 * RSTR; i += THREADS) rAll[i] = 0.f;
    for (int i = tid; i < 8 * 50; i += THREADS) cSlice[i] = 0.f;
    for (int idx = tid; idx < 160 * 50; idx += THREADS) {
        int k = idx / 50, i = idx % 50;
        sWrh[idx] = g_WrhT[k * 200 + 50 * rank + i];
    }
    __syncthreads();
    CLUSTER_SYNC();

    // ---- role-constant hoists ----
    // phase-1 GEMV threads: tid<400, p_b = tid&7 (cluster batch), p_i = tid>>3 (slice row)
    const int p_b = tid & 7;
    const int p_i = tid >> 3;                 // 0..49 valid when tid<400
    const int jg1 = 50 * rank + ((p_i < 50) ? p_i : 0);
    const float brh_r = brh[jg1];
    // combine threads: tid<400, ci = tid%50, cb = tid/50
    const int ci = tid % 50;
    const int cb = tid / 50;                  // 0..7 valid when tid<400
    const int jg = 50 * rank + ci;
    float bh0 = bhh[jg], bh1 = bhh[200 + jg], bh2 = bhh[400 + jg], bh3 = bhh[600 + jg];
    // phase-4 threads: tid<320, fj = tid%40, fb = tid/40
    const int fj = tid % 40;
    const int fb = tid / 40;                  // 0..7 valid when tid<320
    const int jgka = 40 * rank + fj;
    const float bkey_r = bkey[jgka], badd_r = badd[jgka];

    for (int t = 0; t < T_; t++) {
        // ---- prefetch G (combine mapping) ----
        float G0 = 0.f, G1 = 0.f, G2 = 0.f, G3 = 0.f;
        if (tid < 400) {
            const float* Gp = g_G + ((size_t)(bbase + cb) * T_ + t) * G4H;
            G0 = Gp[jg]; G1 = Gp[200 + jg]; G2 = Gp[400 + jg]; G3 = Gp[600 + jg];
        }

        // ---- phase 1: hpre slice GEMV (all 8 b) + broadcast | LRU | prev output ----
        if (tid < 400) {
            const float* rr = &rAll[p_b * RSTR];
            float acc = htAll[p_b * 200 + jg1] + brh_r;
#pragma unroll 8
            for (int k = 0; k < RD; k++) acc += rr[k] * sWrh[k * 50 + p_i];
            bcast_all(&hpreAll[p_b * 200 + jg1], acc);
        } else if (wid == 13 || wid == 14) {
            // stable 4-smallest of wu (owner-local, one warp per b)
            int b = wid - 13;
            unsigned long long kv[4];
            float wl[4];
#pragma unroll
            for (int q = 0; q < 4; q++) {
                int n = lane + 32 * q;
                unsigned u = __float_as_uint(S[b].wu[n]);
                u = (u & 0x80000000u) ? ~u : (u | 0x80000000u);
                kv[q] = ((unsigned long long)u << 32) | (unsigned)n;
                wl[q] = 0.f;
            }
#pragma unroll
            for (int ss = 0; ss < 4; ss++) {
                unsigned long long m = kv[0]; int qi = 0;
#pragma unroll
                for (int q = 1; q < 4; q++) if (kv[q] < m) { m = kv[q]; qi = q; }
                unsigned long long wm = m;
#pragma unroll
                for (int o = 16; o > 0; o >>= 1) {
                    unsigned long long x = __shfl_xor_sync(0xffffffffu, wm, o);
                    if (x < wm) wm = x;
                }
                if (m == wm) { wl[qi] = 1.f; kv[qi] = ~0ull; }
            }
#pragma unroll
            for (int q = 0; q < 4; q++) S[b].wlu[lane + 32 * q] = wl[q];
        } else if (wid == 15 && t > 0) {
            for (int p = 0; p < BPB * NCLS; p++) {
                int b = p / NCLS, cls = p % NCLS;
                const float* rr = S[b].r;
                float acc = 0.f;
#pragma unroll
                for (int k = lane; k < RD; k += 32) acc += rr[k] * Wro[cls * RD + k];
#pragma unroll
                for (int o = 16; o > 0; o >>= 1) acc += __shfl_down_sync(0xffffffffu, acc, o);
                if (lane == 0)
                    out[((size_t)(blk * BPB + b) * T_ + (t - 1)) * NCLS + cls] = acc + S[b].outh[cls];
            }
        }
        CLUSTER_SYNC();   // sync1: hpreAll complete everywhere

        // ---- phase 2 GEMV: gates slice for all 8 b (weights loaded once per cluster) ----
        if (tid < 400) {
            int i2 = tid % 50, ks = tid / 50;        // ks in 0..7, k-range [25ks, 25ks+25)
            float ag[8][4];
#pragma unroll
            for (int b = 0; b < 8; b++)
#pragma unroll
                for (int g = 0; g < 4; g++) ag[b][g] = 0.f;
            const float4* W = reinterpret_cast<const float4*>(g_Wg4) + (50 * rank + i2);
            int k0 = 25 * ks;
#pragma unroll 5
            for (int kk = 0; kk < 25; kk++) {
                int k = k0 + kk;
                float4 w = W[k * 200];
#pragma unroll
                for (int b = 0; b < 8; b++) {
                    float hb = hpreAll[b * 200 + k];
                    ag[b][0] += w.x * hb; ag[b][1] += w.y * hb;
                    ag[b][2] += w.z * hb; ag[b][3] += w.w * hb;
                }
            }
#pragma unroll
            for (int b = 0; b < 8; b++)
#pragma unroll
                for (int g = 0; g < 4; g++)
                    Pbuf[(b * 4 + g) * 400 + ks * 50 + i2] = ag[b][g];
        }
        __syncthreads();

        // ---- phase 2b: combine + LSTM pointwise + h_t broadcast ----
        if (tid < 400) {
            float s0 = G0 + bh0, s1 = G1 + bh1, s2 = G2 + bh2, s3 = G3 + bh3;
#pragma unroll
            for (int ks = 0; ks < 8; ks++) {
                s0 += Pbuf[(cb * 4 + 0) * 400 + ks * 50 + ci];
                s1 += Pbuf[(cb * 4 + 1) * 400 + ks * 50 + ci];
                s2 += Pbuf[(cb * 4 + 2) * 400 + ks * 50 + ci];
                s3 += Pbuf[(cb * 4 + 3) * 400 + ks * 50 + ci];
            }
            float ig = sigmoidf_(s0), fg = sigmoidf_(s1);
            float gg = tanhf(s2),    og = sigmoidf_(s3);
            float ct = fg * cSlice[cb * 50 + ci] + ig * gg;
            cSlice[cb * 50 + ci] = ct;
            float ht = og * tanhf(ct);
            bcast_all(&htAll[cb * 200 + jg], ht);
        }
        CLUSTER_SYNC();   // sync2: htAll complete everywhere

        // ---- phase 4 GEMV: key/add slice for all 8 b | sigma | outh ----
        if (tid < 320) {
            int j = tid % 40, ks = tid / 40;
            float ak[8], aa[8];
#pragma unroll
            for (int b = 0; b < 8; b++) { ak[b] = 0.f; aa[b] = 0.f; }
            const float2* W = reinterpret_cast<const float2*>(g_Wka2) + (40 * rank + j);
            int k0 = 25 * ks;
#pragma unroll 5
            for (int kk = 0; kk < 25; kk++) {
                int k = k0 + kk;
                float2 w = W[k * 160];
#pragma unroll
                for (int b = 0; b < 8; b++) {
                    float hb = htAll[b * 200 + k];
                    ak[b] += w.x * hb; aa[b] += w.y * hb;
                }
            }
#pragma unroll
            for (int b = 0; b < 8; b++) {
                Pbuf[(b * 2 + 0) * 320 + ks * 40 + j] = ak[b];
                Pbuf[(b * 2 + 1) * 320 + ks * 40 + j] = aa[b];
            }
        } else if (wid == 10 || wid == 11) {
            int b = wid - 10;
            const float* hh = &htAll[(rank * 2 + b) * 200];
            float p = 0.f;
            for (int k = lane; k < H_; k += 32) p += hh[k] * Wsig[k];
#pragma unroll
            for (int o = 16; o > 0; o >>= 1) p += __shfl_xor_sync(0xffffffffu, p, o);
            if (lane == 0) S[b].sig = p + bsig[0];
        } else if (wid == 12 || wid == 13) {
            int b = wid - 12;
            const float* hh = &htAll[(rank * 2 + b) * 200];
            for (int cls = 0; cls < NCLS; cls++) {
                float acc = 0.f;
#pragma unroll
                for (int k = lane; k < H_; k += 32) acc += hh[k] * Who[cls * H_ + k];
#pragma unroll
                for (int o = 16; o > 0; o >>= 1) acc += __shfl_down_sync(0xffffffffu, acc, o);
                if (lane == 0) S[b].outh[cls] = acc + bho[cls] + bro[cls];
            }
        }
        __syncthreads();

        // ---- phase 4b: combine + scatter key/add to owners ----
        if (tid < 320) {
            float vk = bkey_r, va = badd_r;
#pragma unroll
            for (int ks = 0; ks < 8; ks++) {
                vk += Pbuf[(fb * 2 + 0) * 320 + ks * 40 + fj];
                va += Pbuf[(fb * 2 + 1) * 320 + ks * 40 + fj];
            }
            int owner = fb >> 1, lb = fb & 1;
            st_rank(&S[lb].key[jgka], vk, owner);
            st_rank(&S[lb].add[jgka], va, owner);
        }
        CLUSTER_SYNC();   // sync3: key/add landed at owners

        // ---- phase 6: M update + wwsum + m2 ; key2 (owner-local, R3-exact) ----
        {
            int b = tid >> 8;
            int n = (tid >> 1) & 127;
            int dh = tid & 1;
            BS& s = S[b];
            float sg = s.sig, omsg = 1.f - sg;
            float wl = s.wlu[n];
            float w0 = sg * s.wr[n]       + omsg * wl;
            float w1 = sg * s.wr[128 + n] + omsg * wl;
            float w2 = sg * s.wr[256 + n] + omsg * wl;
            float w3 = sg * s.wr[384 + n] + omsg * wl;
            if (dh == 0) s.wwsum[n] = w0 + w1 + w2 + w3;
            float m2p = 0.f;
            int d0 = dh * 20;
#pragma unroll
            for (int dd = 0; dd < 20; dd++) {
                int d = d0 + dd;
                float mv = s.M[n * MSTRIDE + d] * wl
                         + w0 * s.add[d] + w1 * s.add[40 + d]
                         + w2 * s.add[80 + d] + w3 * s.add[120 + d];
                s.M[n * MSTRIDE + d] = mv;
                m2p += mv * mv;
            }
            m2p += __shfl_xor_sync(0xffffffffu, m2p, 1);
            if (dh == 0) s.m2[n] = m2p;
        }
        if (tid < 8) {
            int b = tid >> 2, r = tid & 3;
            float sum = 0.f;
#pragma unroll
            for (int d = 0; d < D_; d++) { float v = S[b].key[r * 40 + d]; sum += v * v; }
            S[b].key2[r] = sum;
        }
        __syncthreads();

        // ---- phase 7: cosine similarity ----
        for (int e = tid; e < 1024; e += THREADS) {
            int b = e >> 9, rn = e & 511, r = rn >> 7, n = rn & 127;
            BS& s = S[b];
            const float* kp = s.key + r * 40;
            const float* mp = s.M + n * MSTRIDE;
            float dot = 0.f;
#pragma unroll
            for (int d = 0; d < D_; d++) dot += kp[d] * mp[d];
            s.Ksm[rn] = dot / sqrtf(s.key2[r] * s.m2[n] + 1e-6f);
        }
        __syncthreads();

        // ---- phase 8: softmax over n (warp per (b,r)) ----
        if (wid < 8) {
            int b = wid >> 2, r = wid & 3;
            BS& s = S[b];
            float v0 = s.Ksm[r * N_ + lane];
            float v1 = s.Ksm[r * N_ + 32 + lane];
            float v2 = s.Ksm[r * N_ + 64 + lane];
            float v3 = s.Ksm[r * N_ + 96 + lane];
            float mx = fmaxf(fmaxf(v0, v1), fmaxf(v2, v3));
#pragma unroll
            for (int o = 16; o > 0; o >>= 1) mx = fmaxf(mx, __shfl_xor_sync(0xffffffffu, mx, o));
            float e0 = expf(v0 - mx), e1 = expf(v1 - mx), e2 = expf(v2 - mx), e3 = expf(v3 - mx);
            float su = e0 + e1 + e2 + e3;
#pragma unroll
            for (int o = 16; o > 0; o >>= 1) su += __shfl_xor_sync(0xffffffffu, su, o);
            float inv = 1.f / su;
            s.wr[r * N_ + lane]      = e0 * inv;
            s.wr[r * N_ + 32 + lane] = e1 * inv;
            s.wr[r * N_ + 64 + lane] = e2 * inv;
            s.wr[r * N_ + 96 + lane] = e3 * inv;
        }
        __syncthreads();

        // ---- phase 9: wu update ; phase 10: r_t = wr @ M (+ broadcast r to cluster) ----
        if (tid < 256) {
            int b = tid >> 7, n = tid & 127;
            BS& s = S[b];
            s.wu[n] = 0.95f * s.wu[n]
                    + (s.wr[n] + s.wr[128 + n] + s.wr[256 + n] + s.wr[384 + n])
                    + s.wwsum[n];
        }
        if (tid < 320) {
            int b = tid / 160, rd = tid % 160;
            int r = rd / 40, d = rd % 40;
            BS& s = S[b];
            const float* wrp = s.wr + r * N_;
            float dot = 0.f;
#pragma unroll 8
            for (int n = 0; n < N_; n++) dot += wrp[n] * s.M[n * MSTRIDE + d];
            s.r[rd] = dot;
            bcast_all(&rAll[(rank * 2 + b) * RSTR + rd], dot);
        }
        CLUSTER_SYNC();   // sync4: rAll complete before next step's phase 1
    }

    // ---- final output (t = 99) ----
    if (wid == 15) {
        for (int p = 0; p < BPB * NCLS; p++) {
            int b = p / NCLS, cls = p % NCLS;
            const float* rr = S[b].r;
            float acc = 0.f;
#pragma unroll
            for (int k = lane; k < RD; k += 32) acc += rr[k] * Wro[cls * RD + k];
#pragma unroll
            for (int o = 16; o > 0; o >>= 1) acc += __shfl_down_sync(0xffffffffu, acc, o);
            if (lane == 0)
                out[((size_t)(blk * BPB + b) * T_ + (T_ - 1)) * NCLS + cls] = acc + S[b].outh[cls];
        }
    }
}

// ---------------- launch ----------------
extern "C" void kernel_launch(void* const* d_in, const int* in_sizes, int n_in,
                              void* d_out, int out_size) {
    const float* x    = (const float*)d_in[0];
    const float* Wkey = (const float*)d_in[1];
    const float* bkey = (const float*)d_in[2];
    const float* Wadd = (const float*)d_in[3];
    const float* badd = (const float*)d_in[4];
    const float* Wsig = (const float*)d_in[5];
    const float* bsig = (const float*)d_in[6];
    const float* Who  = (const float*)d_in[7];
    const float* bho  = (const float*)d_in[8];
    const float* Wro  = (const float*)d_in[9];
    const float* bro  = (const float*)d_in[10];
    const float* Wrh  = (const float*)d_in[11];
    const float* brh  = (const float*)d_in[12];
    const float* Wih  = (const float*)d_in[13];
    const float* bih  = (const float*)d_in[14];
    const float* Whh  = (const float*)d_in[15];
    const float* bhh  = (const float*)d_in[16];
    float* out = (float*)d_out;

    prep_weights<<<1000, 256>>>(Whh, Wkey, Wadd, Wrh);
    gemm_gates_x<<<dim3((G4H + GBN - 1) / GBN, B_ * T_ / GBM), 256>>>(x, Wih, bih);

    size_t shmem = (size_t)SMEM_FLOATS * 4;
    cudaFuncSetAttribute(mann_recurrent, cudaFuncAttributeMaxDynamicSharedMemorySize, (int)shmem);
    mann_recurrent<<<NBLK, THREADS, shmem>>>(bkey, badd, Wsig, bsig, Who, bho,
                                             Wro, bro, brh, bhh, out);
}

// round 7
// speedup vs baseline: 2.2853x; 1.0691x over previous
#include <cuda_runtime.h>
#include <math.h>
#include <stdint.h>

#define B_    256
#define T_    100
#define IN_   784
#define H_    200
#define R_    4
#define N_    128
#define D_    40
#define NCLS  5
#define G4H   800
#define RD    160
#define MSTRIDE 41
#define RSTR  164

#define BPB   2
#define NBLK  (B_/BPB)
#define THREADS 512
#define CS    4

// ---------------- device scratch ----------------
__device__ float g_G[B_*T_*G4H];
__device__ float g_Wg4[H_*H_*4];
__device__ float g_Wka2[H_*RD*2];
__device__ float g_WrhT[RD*H_];

// ---------------- cluster helpers ----------------
__device__ __forceinline__ unsigned ctarank() {
    unsigned r; asm("mov.u32 %0, %%cluster_ctarank;" : "=r"(r)); return r;
}
__device__ __forceinline__ void bcast_all(void* p, float v) {
    unsigned a = (unsigned)__cvta_generic_to_shared(p);
#pragma unroll
    for (int r = 0; r < CS; r++) {
        unsigned ra;
        asm("mapa.shared::cluster.u32 %0, %1, %2;" : "=r"(ra) : "r"(a), "r"(r));
        asm volatile("st.shared::cluster.f32 [%0], %1;" :: "r"(ra), "f"(v));
    }
}
__device__ __forceinline__ void st_rank(void* p, float v, int r) {
    unsigned a = (unsigned)__cvta_generic_to_shared(p);
    unsigned ra;
    asm("mapa.shared::cluster.u32 %0, %1, %2;" : "=r"(ra) : "r"(a), "r"(r));
    asm volatile("st.shared::cluster.f32 [%0], %1;" :: "r"(ra), "f"(v));
}
#define CLUSTER_SYNC() do { \
    asm volatile("barrier.cluster.arrive.aligned;" ::: "memory"); \
    asm volatile("barrier.cluster.wait.aligned;"   ::: "memory"); \
} while (0)

// ---------------- weight repack ----------------
__global__ void prep_weights(const float* __restrict__ Whh,
                             const float* __restrict__ Wkey,
                             const float* __restrict__ Wadd,
                             const float* __restrict__ Wrh) {
    int i = blockIdx.x * 256 + threadIdx.x;
    if (i < 160000) {
        int k = i / 800, rem = i % 800, ii = rem >> 2, g = rem & 3;
        g_Wg4[i] = Whh[(g * 200 + ii) * 200 + k];
    } else if (i < 224000) {
        int z = i - 160000;
        int k = z / 320, rem = z % 320, j = rem >> 1, w = rem & 1;
        g_Wka2[z] = w ? Wadd[j * 200 + k] : Wkey[j * 200 + k];
    } else if (i < 256000) {
        int z = i - 224000; int k = z / 200, j = z % 200;
        g_WrhT[z] = Wrh[j * 160 + k];
    }
}

// ---------------- big input GEMM: G = x @ Wih^T + bih ----------------
// 128x128 tile, 8x8 micro-tile with float4 smem loads, double-buffered, 1 sync/iter.
#define GBM 128
#define GBN 128
#define GBK 16
#define TSTR 132   // tile row stride (floats), 16B-aligned

__global__ __launch_bounds__(256) void gemm_gates_x(
    const float* __restrict__ X, const float* __restrict__ Wih,
    const float* __restrict__ bih) {
    __shared__ float As[2][GBK][TSTR];
    __shared__ float Bs[2][GBK][TSTR];
    const int tid = threadIdx.x;
    const int m0 = blockIdx.y * GBM;
    const int n0 = blockIdx.x * GBN;
    const int tx = tid & 15, ty = tid >> 4;   // micro-tile coords

    float acc[8][8];
#pragma unroll
    for (int i = 0; i < 8; i++)
#pragma unroll
        for (int j = 0; j < 8; j++) acc[i][j] = 0.f;

    const int ar = tid >> 1, ac = (tid & 1) * 8;   // loader coords
    const int bn = n0 + ar;
    const float* Asrc = X + (size_t)(m0 + ar) * IN_ + ac;
    const float* Bsrc = (bn < G4H) ? (Wih + (size_t)bn * IN_ + ac) : nullptr;

    float a[8], b[8];
    // initial tile load (kt = 0)
    {
        float4 v0 = *(const float4*)(Asrc);
        float4 v1 = *(const float4*)(Asrc + 4);
        a[0]=v0.x; a[1]=v0.y; a[2]=v0.z; a[3]=v0.w;
        a[4]=v1.x; a[5]=v1.y; a[6]=v1.z; a[7]=v1.w;
        float4 w0 = make_float4(0.f,0.f,0.f,0.f), w1 = w0;
        if (Bsrc) { w0 = *(const float4*)(Bsrc); w1 = *(const float4*)(Bsrc + 4); }
        b[0]=w0.x; b[1]=w0.y; b[2]=w0.z; b[3]=w0.w;
        b[4]=w1.x; b[5]=w1.y; b[6]=w1.z; b[7]=w1.w;
#pragma unroll
        for (int i = 0; i < 8; i++) { As[0][ac + i][ar] = a[i]; Bs[0][ac + i][ar] = b[i]; }
    }
    __syncthreads();

    int cur = 0;
    for (int kt = 0; kt < IN_; kt += GBK) {
        const bool have_next = (kt + GBK < IN_);
        if (have_next) {
            const float* as = Asrc + kt + GBK;
            float4 v0 = *(const float4*)(as);
            float4 v1 = *(const float4*)(as + 4);
            a[0]=v0.x; a[1]=v0.y; a[2]=v0.z; a[3]=v0.w;
            a[4]=v1.x; a[5]=v1.y; a[6]=v1.z; a[7]=v1.w;
            float4 w0 = make_float4(0.f,0.f,0.f,0.f), w1 = w0;
            if (Bsrc) {
                const float* bs = Bsrc + kt + GBK;
                w0 = *(const float4*)(bs); w1 = *(const float4*)(bs + 4);
            }
            b[0]=w0.x; b[1]=w0.y; b[2]=w0.z; b[3]=w0.w;
            b[4]=w1.x; b[5]=w1.y; b[6]=w1.z; b[7]=w1.w;
        }
#pragma unroll
        for (int k = 0; k < GBK; k++) {
            float4 a0 = *(const float4*)&As[cur][k][8 * ty];
            float4 a1 = *(const float4*)&As[cur][k][8 * ty + 4];
            float4 b0 = *(const float4*)&Bs[cur][k][8 * tx];
            float4 b1 = *(const float4*)&Bs[cur][k][8 * tx + 4];
            float ra[8] = {a0.x,a0.y,a0.z,a0.w,a1.x,a1.y,a1.z,a1.w};
            float rb[8] = {b0.x,b0.y,b0.z,b0.w,b1.x,b1.y,b1.z,b1.w};
#pragma unroll
            for (int i = 0; i < 8; i++)
#pragma unroll
                for (int j = 0; j < 8; j++) acc[i][j] += ra[i] * rb[j];
        }
        if (have_next) {
            int nxt = cur ^ 1;
#pragma unroll
            for (int i = 0; i < 8; i++) { As[nxt][ac + i][ar] = a[i]; Bs[nxt][ac + i][ar] = b[i]; }
        }
        __syncthreads();
        cur ^= 1;
    }

    float bihr[8];
#pragma unroll
    for (int j = 0; j < 8; j++) {
        int gn = n0 + 8 * tx + j;
        bihr[j] = (gn < G4H) ? bih[gn] : 0.f;
    }
#pragma unroll
    for (int i = 0; i < 8; i++) {
        size_t base = (size_t)(m0 + 8 * ty + i) * G4H;
        int col = n0 + 8 * tx;
        if (col < G4H) {
            float4 o0 = make_float4(acc[i][0]+bihr[0], acc[i][1]+bihr[1],
                                    acc[i][2]+bihr[2], acc[i][3]+bihr[3]);
            float4 o1 = make_float4(acc[i][4]+bihr[4], acc[i][5]+bihr[5],
                                    acc[i][6]+bihr[6], acc[i][7]+bihr[7]);
            *(float4*)&g_G[base + col]     = o0;
            *(float4*)&g_G[base + col + 4] = o1;
        }
    }
}

// ---------------- recurrent kernel (R6, byte-identical) ----------------
struct __align__(16) BS {
    float M[N_ * MSTRIDE];
    float r[RD];
    float key[RD];
    float add[RD];
    float wr[R_ * N_];
    float wu[N_];
    float wwsum[N_];
    float Ksm[R_ * N_];
    float m2[N_];
    float wlu[N_];
    float outh[NCLS];
    float key2[R_];
    float sig;
    float pad_[2];
};
#define BSF (sizeof(BS)/4)

#define OFF_SWRH   (2*BSF)
#define OFF_HPRE   (OFF_SWRH + 8000)
#define OFF_HT     (OFF_HPRE + 1600)
#define OFF_RALL   (OFF_HT   + 1600)
#define OFF_CSL    (OFF_RALL + 1312)
#define OFF_PBUF   (OFF_CSL  + 400)
#define SMEM_FLOATS (OFF_PBUF + 12800)

__device__ __forceinline__ float sigmoidf_(float x) { return 1.f / (1.f + expf(-x)); }

__global__ __launch_bounds__(THREADS) __cluster_dims__(CS, 1, 1)
void mann_recurrent(
    const float* __restrict__ bkey, const float* __restrict__ badd,
    const float* __restrict__ Wsig, const float* __restrict__ bsig,
    const float* __restrict__ Who,  const float* __restrict__ bho,
    const float* __restrict__ Wro,  const float* __restrict__ bro,
    const float* __restrict__ brh,  const float* __restrict__ bhh,
    float* __restrict__ out) {
    extern __shared__ float smemf[];
    BS* S          = reinterpret_cast<BS*>(smemf);
    float* sWrh    = smemf + OFF_SWRH;
    float* hpreAll = smemf + OFF_HPRE;
    float* htAll   = smemf + OFF_HT;
    float* rAll    = smemf + OFF_RALL;
    float* cSlice  = smemf + OFF_CSL;
    float* Pbuf    = smemf + OFF_PBUF;

    const int tid  = threadIdx.x;
    const int blk  = blockIdx.x;
    const int wid  = tid >> 5, lane = tid & 31;
    const unsigned rank = ctarank();
    const int bbase = (blk >> 2) * 8;

    for (int b = 0; b < BPB; b++) {
        BS& s = S[b];
        for (int i = tid; i < N_ * MSTRIDE; i += THREADS) s.M[i] = 0.f;
        for (int i = tid; i < RD; i += THREADS) s.r[i] = 0.f;
        for (int i = tid; i < R_ * N_; i += THREADS) s.wr[i] = 0.f;
        for (int i = tid; i < N_; i += THREADS) s.wu[i] = 0.f;
    }
    for (int i = tid; i < 8 * 200; i += THREADS) htAll[i] = 0.f;
    for (int i = tid; i < 8 * RSTR; i += THREADS) rAll[i] = 0.f;
    for (int i = tid; i < 8 * 50; i += THREADS) cSlice[i] = 0.f;
    for (int idx = tid; idx < 160 * 50; idx += THREADS) {
        int k = idx / 50, i = idx % 50;
        sWrh[idx] = g_WrhT[k * 200 + 50 * rank + i];
    }
    __syncthreads();
    CLUSTER_SYNC();

    const int p_b = tid & 7;
    const int p_i = tid >> 3;
    const int jg1 = 50 * rank + ((p_i < 50) ? p_i : 0);
    const float brh_r = brh[jg1];
    const int ci = tid % 50;
    const int cb = tid / 50;
    const int jg = 50 * rank + ci;
    float bh0 = bhh[jg], bh1 = bhh[200 + jg], bh2 = bhh[400 + jg], bh3 = bhh[600 + jg];
    const int fj = tid % 40;
    const int fb = tid / 40;
    const int jgka = 40 * rank + fj;
    const float bkey_r = bkey[jgka], badd_r = badd[jgka];

    for (int t = 0; t < T_; t++) {
        float G0 = 0.f, G1 = 0.f, G2 = 0.f, G3 = 0.f;
        if (tid < 400) {
            const float* Gp = g_G + ((size_t)(bbase + cb) * T_ + t) * G4H;
            G0 = Gp[jg]; G1 = Gp[200 + jg]; G2 = Gp[400 + jg]; G3 = Gp[600 + jg];
        }

        if (tid < 400) {
            const float* rr = &rAll[p_b * RSTR];
            float acc = htAll[p_b * 200 + jg1] + brh_r;
#pragma unroll 8
            for (int k = 0; k < RD; k++) acc += rr[k] * sWrh[k * 50 + p_i];
            bcast_all(&hpreAll[p_b * 200 + jg1], acc);
        } else if (wid == 13 || wid == 14) {
            int b = wid - 13;
            unsigned long long kv[4];
            float wl[4];
#pragma unroll
            for (int q = 0; q < 4; q++) {
                int n = lane + 32 * q;
                unsigned u = __float_as_uint(S[b].wu[n]);
                u = (u & 0x80000000u) ? ~u : (u | 0x80000000u);
                kv[q] = ((unsigned long long)u << 32) | (unsigned)n;
                wl[q] = 0.f;
            }
#pragma unroll
            for (int ss = 0; ss < 4; ss++) {
                unsigned long long m = kv[0]; int qi = 0;
#pragma unroll
                for (int q = 1; q < 4; q++) if (kv[q] < m) { m = kv[q]; qi = q; }
                unsigned long long wm = m;
#pragma unroll
                for (int o = 16; o > 0; o >>= 1) {
                    unsigned long long x = __shfl_xor_sync(0xffffffffu, wm, o);
                    if (x < wm) wm = x;
                }
                if (m == wm) { wl[qi] = 1.f; kv[qi] = ~0ull; }
            }
#pragma unroll
            for (int q = 0; q < 4; q++) S[b].wlu[lane + 32 * q] = wl[q];
        } else if (wid == 15 && t > 0) {
            for (int p = 0; p < BPB * NCLS; p++) {
                int b = p / NCLS, cls = p % NCLS;
                const float* rr = S[b].r;
                float acc = 0.f;
#pragma unroll
                for (int k = lane; k < RD; k += 32) acc += rr[k] * Wro[cls * RD + k];
#pragma unroll
                for (int o = 16; o > 0; o >>= 1) acc += __shfl_down_sync(0xffffffffu, acc, o);
                if (lane == 0)
                    out[((size_t)(blk * BPB + b) * T_ + (t - 1)) * NCLS + cls] = acc + S[b].outh[cls];
            }
        }
        CLUSTER_SYNC();

        if (tid < 400) {
            int i2 = tid % 50, ks = tid / 50;
            float ag[8][4];
#pragma unroll
            for (int b = 0; b < 8; b++)
#pragma unroll
                for (int g = 0; g < 4; g++) ag[b][g] = 0.f;
            const float4* W = reinterpret_cast<const float4*>(g_Wg4) + (50 * rank + i2);
            int k0 = 25 * ks;
#pragma unroll 5
            for (int kk = 0; kk < 25; kk++) {
                int k = k0 + kk;
                float4 w = W[k * 200];
#pragma unroll
                for (int b = 0; b < 8; b++) {
                    float hb = hpreAll[b * 200 + k];
                    ag[b][0] += w.x * hb; ag[b][1] += w.y * hb;
                    ag[b][2] += w.z * hb; ag[b][3] += w.w * hb;
                }
            }
#pragma unroll
            for (int b = 0; b < 8; b++)
#pragma unroll
                for (int g = 0; g < 4; g++)
                    Pbuf[(b * 4 + g) * 400 + ks * 50 + i2] = ag[b][g];
        }
        __syncthreads();

        if (tid < 400) {
            float s0 = G0 + bh0, s1 = G1 + bh1, s2 = G2 + bh2, s3 = G3 + bh3;
#pragma unroll
            for (int ks = 0; ks < 8; ks++) {
                s0 += Pbuf[(cb * 4 + 0) * 400 + ks * 50 + ci];
                s1 += Pbuf[(cb * 4 + 1) * 400 + ks * 50 + ci];
                s2 += Pbuf[(cb * 4 + 2) * 400 + ks * 50 + ci];
                s3 += Pbuf[(cb * 4 + 3) * 400 + ks * 50 + ci];
            }
            float ig = sigmoidf_(s0), fg = sigmoidf_(s1);
            float gg = tanhf(s2),    og = sigmoidf_(s3);
            float ct = fg * cSlice[cb * 50 + ci] + ig * gg;
            cSlice[cb * 50 + ci] = ct;
            float ht = og * tanhf(ct);
            bcast_all(&htAll[cb * 200 + jg], ht);
        }
        CLUSTER_SYNC();

        if (tid < 320) {
            int j = tid % 40, ks = tid / 40;
            float ak[8], aa[8];
#pragma unroll
            for (int b = 0; b < 8; b++) { ak[b] = 0.f; aa[b] = 0.f; }
            const float2* W = reinterpret_cast<const float2*>(g_Wka2) + (40 * rank + j);
            int k0 = 25 * ks;
#pragma unroll 5
            for (int kk = 0; kk < 25; kk++) {
                int k = k0 + kk;
                float2 w = W[k * 160];
#pragma unroll
                for (int b = 0; b < 8; b++) {
                    float hb = htAll[b * 200 + k];
                    ak[b] += w.x * hb; aa[b] += w.y * hb;
                }
            }
#pragma unroll
            for (int b = 0; b < 8; b++) {
                Pbuf[(b * 2 + 0) * 320 + ks * 40 + j] = ak[b];
                Pbuf[(b * 2 + 1) * 320 + ks * 40 + j] = aa[b];
            }
        } else if (wid == 10 || wid == 11) {
            int b = wid - 10;
            const float* hh = &htAll[(rank * 2 + b) * 200];
            float p = 0.f;
            for (int k = lane; k < H_; k += 32) p += hh[k] * Wsig[k];
#pragma unroll
            for (int o = 16; o > 0; o >>= 1) p += __shfl_xor_sync(0xffffffffu, p, o);
            if (lane == 0) S[b].sig = p + bsig[0];
        } else if (wid == 12 || wid == 13) {
            int b = wid - 12;
            const float* hh = &htAll[(rank * 2 + b) * 200];
            for (int cls = 0; cls < NCLS; cls++) {
                float acc = 0.f;
#pragma unroll
                for (int k = lane; k < H_; k += 32) acc += hh[k] * Who[cls * H_ + k];
#pragma unroll
                for (int o = 16; o > 0; o >>= 1) acc += __shfl_down_sync(0xffffffffu, acc, o);
                if (lane == 0) S[b].outh[cls] = acc + bho[cls] + bro[cls];
            }
        }
        __syncthreads();

        if (tid < 320) {
            float vk = bkey_r, va = badd_r;
#pragma unroll
            for (int ks = 0; ks < 8; ks++) {
                vk += Pbuf[(fb * 2 + 0) * 320 + ks * 40 + fj];
                va += Pbuf[(fb * 2 + 1) * 320 + ks * 40 + fj];
            }
            int owner = fb >> 1, lb = fb & 1;
            st_rank(&S[lb].key[jgka], vk, owner);
            st_rank(&S[lb].add[jgka], va, owner);
        }
        CLUSTER_SYNC();

        {
            int b = tid >> 8;
            int n = (tid >> 1) & 127;
            int dh = tid & 1;
            BS& s = S[b];
            float sg = s.sig, omsg = 1.f - sg;
            float wl = s.wlu[n];
            float w0 = sg * s.wr[n]       + omsg * wl;
            float w1 = sg * s.wr[128 + n] + omsg * wl;
            float w2 = sg * s.wr[256 + n] + omsg * wl;
            float w3 = sg * s.wr[384 + n] + omsg * wl;
            if (dh == 0) s.wwsum[n] = w0 + w1 + w2 + w3;
            float m2p = 0.f;
            int d0 = dh * 20;
#pragma unroll
            for (int dd = 0; dd < 20; dd++) {
                int d = d0 + dd;
                float mv = s.M[n * MSTRIDE + d] * wl
                         + w0 * s.add[d] + w1 * s.add[40 + d]
                         + w2 * s.add[80 + d] + w3 * s.add[120 + d];
                s.M[n * MSTRIDE + d] = mv;
                m2p += mv * mv;
            }
            m2p += __shfl_xor_sync(0xffffffffu, m2p, 1);
            if (dh == 0) s.m2[n] = m2p;
        }
        if (tid < 8) {
            int b = tid >> 2, r = tid & 3;
            float sum = 0.f;
#pragma unroll
            for (int d = 0; d < D_; d++) { float v = S[b].key[r * 40 + d]; sum += v * v; }
            S[b].key2[r] = sum;
        }
        __syncthreads();

        for (int e = tid; e < 1024; e += THREADS) {
            int b = e >> 9, rn = e & 511, r = rn >> 7, n = rn & 127;
            BS& s = S[b];
            const float* kp = s.key + r * 40;
            const float* mp = s.M + n * MSTRIDE;
            float dot = 0.f;
#pragma unroll
            for (int d = 0; d < D_; d++) dot += kp[d] * mp[d];
            s.Ksm[rn] = dot / sqrtf(s.key2[r] * s.m2[n] + 1e-6f);
        }
        __syncthreads();

        if (wid < 8) {
            int b = wid >> 2, r = wid & 3;
            BS& s = S[b];
            float v0 = s.Ksm[r * N_ + lane];
            float v1 = s.Ksm[r * N_ + 32 + lane];
            float v2 = s.Ksm[r * N_ + 64 + lane];
            float v3 = s.Ksm[r * N_ + 96 + lane];
            float mx = fmaxf(fmaxf(v0, v1), fmaxf(v2, v3));
#pragma unroll
            for (int o = 16; o > 0; o >>= 1) mx = fmaxf(mx, __shfl_xor_sync(0xffffffffu, mx, o));
            float e0 = expf(v0 - mx), e1 = expf(v1 - mx), e2 = expf(v2 - mx), e3 = expf(v3 - mx);
            float su = e0 + e1 + e2 + e3;
#pragma unroll
            for (int o = 16; o > 0; o >>= 1) su += __shfl_xor_sync(0xffffffffu, su, o);
            float inv = 1.f / su;
            s.wr[r * N_ + lane]      = e0 * inv;
            s.wr[r * N_ + 32 + lane] = e1 * inv;
            s.wr[r * N_ + 64 + lane] = e2 * inv;
            s.wr[r * N_ + 96 + lane] = e3 * inv;
        }
        __syncthreads();

        if (tid < 256) {
            int b = tid >> 7, n = tid & 127;
            BS& s = S[b];
            s.wu[n] = 0.95f * s.wu[n]
                    + (s.wr[n] + s.wr[128 + n] + s.wr[256 + n] + s.wr[384 + n])
                    + s.wwsum[n];
        }
        if (tid < 320) {
            int b = tid / 160, rd = tid % 160;
            int r = rd / 40, d = rd % 40;
            BS& s = S[b];
            const float* wrp = s.wr + r * N_;
            float dot = 0.f;
#pragma unroll 8
            for (int n = 0; n < N_; n++) dot += wrp[n] * s.M[n * MSTRIDE + d];
            s.r[rd] = dot;
            bcast_all(&rAll[(rank * 2 + b) * RSTR + rd], dot);
        }
        CLUSTER_SYNC();
    }

    if (wid == 15) {
        for (int p = 0; p < BPB * NCLS; p++) {
            int b = p / NCLS, cls = p % NCLS;
            const float* rr = S[b].r;
            float acc = 0.f;
#pragma unroll
            for (int k = lane; k < RD; k += 32) acc += rr[k] * Wro[cls * RD + k];
#pragma unroll
            for (int o = 16; o > 0; o >>= 1) acc += __shfl_down_sync(0xffffffffu, acc, o);
            if (lane == 0)
                out[((size_t)(blk * BPB + b) * T_ + (T_ - 1)) * NCLS + cls] = acc + S[b].outh[cls];
        }
    }
}

// ---------------- launch ----------------
extern "C" void kernel_launch(void* const* d_in, const int* in_sizes, int n_in,
                              void* d_out, int out_size) {
    const float* x    = (const float*)d_in[0];
    const float* Wkey = (const float*)d_in[1];
    const float* bkey = (const float*)d_in[2];
    const float* Wadd = (const float*)d_in[3];
    const float* badd = (const float*)d_in[4];
    const float* Wsig = (const float*)d_in[5];
    const float* bsig = (const float*)d_in[6];
    const float* Who  = (const float*)d_in[7];
    const float* bho  = (const float*)d_in[8];
    const float* Wro  = (const float*)d_in[9];
    const float* bro  = (const float*)d_in[10];
    const float* Wrh  = (const float*)d_in[11];
    const float* brh  = (const float*)d_in[12];
    const float* Wih  = (const float*)d_in[13];
    const float* bih  = (const float*)d_in[14];
    const float* Whh  = (const float*)d_in[15];
    const float* bhh  = (const float*)d_in[16];
    float* out = (float*)d_out;

    prep_weights<<<1000, 256>>>(Whh, Wkey, Wadd, Wrh);
    gemm_gates_x<<<dim3((G4H + GBN - 1) / GBN, B_ * T_ / GBM), 256>>>(x, Wih, bih);

    size_t shmem = (size_t)SMEM_FLOATS * 4;
    cudaFuncSetAttribute(mann_recurrent, cudaFuncAttributeMaxDynamicSharedMemorySize, (int)shmem);
    mann_recurrent<<<NBLK, THREADS, shmem>>>(bkey, badd, Wsig, bsig, Who, bho,
                                             Wro, bro, brh, bhh, out);
}

// round 8
// speedup vs baseline: 2.4739x; 1.0825x over previous
#include <cuda_runtime.h>
#include <math.h>
#include <stdint.h>

#define B_    256
#define T_    100
#define IN_   784
#define H_    200
#define R_    4
#define N_    128
#define D_    40
#define NCLS  5
#define G4H   800
#define RD    160
#define MSTRIDE 41
#define RSTR  164

#define BPB   2
#define NBLK  (B_/BPB)
#define THREADS 512
#define CS    4

// ---------------- device scratch ----------------
__device__ float g_G[B_*T_*G4H];
__device__ float g_Wg4[H_*H_*4];
__device__ float g_Wka2[H_*RD*2];
__device__ float g_WrhT[RD*H_];

// ---------------- cluster helpers ----------------
__device__ __forceinline__ unsigned ctarank() {
    unsigned r; asm("mov.u32 %0, %%cluster_ctarank;" : "=r"(r)); return r;
}
__device__ __forceinline__ void bcast_all(void* p, float v) {
    unsigned a = (unsigned)__cvta_generic_to_shared(p);
#pragma unroll
    for (int r = 0; r < CS; r++) {
        unsigned ra;
        asm("mapa.shared::cluster.u32 %0, %1, %2;" : "=r"(ra) : "r"(a), "r"(r));
        asm volatile("st.shared::cluster.f32 [%0], %1;" :: "r"(ra), "f"(v));
    }
}
__device__ __forceinline__ void st_rank(void* p, float v, int r) {
    unsigned a = (unsigned)__cvta_generic_to_shared(p);
    unsigned ra;
    asm("mapa.shared::cluster.u32 %0, %1, %2;" : "=r"(ra) : "r"(a), "r"(r));
    asm volatile("st.shared::cluster.f32 [%0], %1;" :: "r"(ra), "f"(v));
}
#define CLUSTER_SYNC() do { \
    asm volatile("barrier.cluster.arrive.aligned;" ::: "memory"); \
    asm volatile("barrier.cluster.wait.aligned;"   ::: "memory"); \
} while (0)

// ---------------- weight repack ----------------
__global__ void prep_weights(const float* __restrict__ Whh,
                             const float* __restrict__ Wkey,
                             const float* __restrict__ Wadd,
                             const float* __restrict__ Wrh) {
    int i = blockIdx.x * 256 + threadIdx.x;
    if (i < 160000) {
        int k = i / 800, rem = i % 800, ii = rem >> 2, g = rem & 3;
        g_Wg4[i] = Whh[(g * 200 + ii) * 200 + k];
    } else if (i < 224000) {
        int z = i - 160000;
        int k = z / 320, rem = z % 320, j = rem >> 1, w = rem & 1;
        g_Wka2[z] = w ? Wadd[j * 200 + k] : Wkey[j * 200 + k];
    } else if (i < 256000) {
        int z = i - 224000; int k = z / 200, j = z % 200;
        g_WrhT[z] = Wrh[j * 160 + k];
    }
}

// ---------------- big input GEMM: split-TF32 tensor-core mma.sync ----------------
// G[m][n] = sum_k X[m][k] * Wih[n][k] + bih[n];  M=25600, N=800, K=784
// Block 128x128, 8 warps (warp tile 32x64), K-tile 16, SMEM [k][m] stride 136.
#define GTM 128
#define GTN 128
#define GTK 16
#define GSTR 136

__device__ __forceinline__ uint32_t f2tf32(float v) {
    uint32_t r; asm("cvt.rna.tf32.f32 %0, %1;" : "=r"(r) : "f"(v)); return r;
}
#define MMA_TF32(D, A, B0, B1) \
    asm volatile("mma.sync.aligned.m16n8k8.row.col.f32.tf32.tf32.f32 " \
                 "{%0,%1,%2,%3}, {%4,%5,%6,%7}, {%8,%9}, {%0,%1,%2,%3};" \
                 : "+f"((D)[0]), "+f"((D)[1]), "+f"((D)[2]), "+f"((D)[3]) \
                 : "r"((A)[0]), "r"((A)[1]), "r"((A)[2]), "r"((A)[3]), \
                   "r"(B0), "r"(B1))

__global__ __launch_bounds__(256) void gemm_gates_x(
    const float* __restrict__ X, const float* __restrict__ Wih,
    const float* __restrict__ bih) {
    __shared__ uint32_t Ah[GTK][GSTR], Al[GTK][GSTR];
    __shared__ uint32_t Bh[GTK][GSTR], Bl[GTK][GSTR];

    const int tid = threadIdx.x;
    const int m0 = blockIdx.y * GTM;
    const int n0 = blockIdx.x * GTN;
    const int wid = tid >> 5, lane = tid & 31;
    const int g = lane >> 2, l = lane & 3;
    const int wm = (wid >> 1) * 32;     // warp row offset in tile
    const int wn = (wid & 1) * 64;      // warp col offset in tile

    float d[2][8][4];
#pragma unroll
    for (int mf = 0; mf < 2; mf++)
#pragma unroll
        for (int nf = 0; nf < 8; nf++)
#pragma unroll
            for (int q = 0; q < 4; q++) d[mf][nf][q] = 0.f;

    // loader mapping: 128 rows x 16 k, 8 floats per thread
    const int ar = tid >> 1, ac = (tid & 1) * 8;
    const float* Asrc = X + (size_t)(m0 + ar) * IN_ + ac;
    const bool bvalid = (n0 + ar) < G4H;
    const float* Bsrc = bvalid ? (Wih + (size_t)(n0 + ar) * IN_ + ac) : nullptr;

    for (int kt = 0; kt < IN_; kt += GTK) {
        __syncthreads();   // previous tile fully consumed
        {
            float4 v0 = *(const float4*)(Asrc + kt);
            float4 v1 = *(const float4*)(Asrc + kt + 4);
            float av[8] = {v0.x,v0.y,v0.z,v0.w,v1.x,v1.y,v1.z,v1.w};
            float4 w0 = make_float4(0.f,0.f,0.f,0.f), w1 = w0;
            if (bvalid) { w0 = *(const float4*)(Bsrc + kt); w1 = *(const float4*)(Bsrc + kt + 4); }
            float bv[8] = {w0.x,w0.y,w0.z,w0.w,w1.x,w1.y,w1.z,w1.w};
#pragma unroll
            for (int i = 0; i < 8; i++) {
                uint32_t ahi = f2tf32(av[i]);
                float alo = av[i] - __uint_as_float(ahi);
                Ah[ac + i][ar] = ahi;
                Al[ac + i][ar] = f2tf32(alo);
                uint32_t bhi = f2tf32(bv[i]);
                float blo = bv[i] - __uint_as_float(bhi);
                Bh[ac + i][ar] = bhi;
                Bl[ac + i][ar] = f2tf32(blo);
            }
        }
        __syncthreads();

#pragma unroll
        for (int k8 = 0; k8 < 2; k8++) {
            const int kr = 8 * k8;
            uint32_t ah[2][4], al_[2][4];
#pragma unroll
            for (int mf = 0; mf < 2; mf++) {
                int base = wm + 16 * mf;
                ah[mf][0]  = Ah[kr + l][base + g];
                ah[mf][1]  = Ah[kr + l][base + g + 8];
                ah[mf][2]  = Ah[kr + l + 4][base + g];
                ah[mf][3]  = Ah[kr + l + 4][base + g + 8];
                al_[mf][0] = Al[kr + l][base + g];
                al_[mf][1] = Al[kr + l][base + g + 8];
                al_[mf][2] = Al[kr + l + 4][base + g];
                al_[mf][3] = Al[kr + l + 4][base + g + 8];
            }
#pragma unroll
            for (int nf = 0; nf < 8; nf++) {
                int nb = wn + 8 * nf;
                uint32_t bh0 = Bh[kr + l][nb + g];
                uint32_t bh1 = Bh[kr + l + 4][nb + g];
                uint32_t bl0 = Bl[kr + l][nb + g];
                uint32_t bl1 = Bl[kr + l + 4][nb + g];
#pragma unroll
                for (int mf = 0; mf < 2; mf++) {
                    MMA_TF32(d[mf][nf], ah[mf],  bh0, bh1);   // hi*hi
                    MMA_TF32(d[mf][nf], al_[mf], bh0, bh1);   // lo*hi
                    MMA_TF32(d[mf][nf], ah[mf],  bl0, bl1);   // hi*lo
                }
            }
        }
    }

    // epilogue: d[mf][nf]: rows g / g+8 within frag, cols 2l / 2l+1
#pragma unroll
    for (int mf = 0; mf < 2; mf++) {
#pragma unroll
        for (int nf = 0; nf < 8; nf++) {
            int col = n0 + wn + 8 * nf + 2 * l;
            if (col < G4H) {
                float b0 = bih[col], b1 = bih[col + 1];
                int row0 = m0 + wm + 16 * mf + g;
                float2 o0 = make_float2(d[mf][nf][0] + b0, d[mf][nf][1] + b1);
                float2 o1 = make_float2(d[mf][nf][2] + b0, d[mf][nf][3] + b1);
                *(float2*)&g_G[(size_t)row0 * G4H + col]       = o0;
                *(float2*)&g_G[(size_t)(row0 + 8) * G4H + col] = o1;
            }
        }
    }
}

// ---------------- recurrent kernel (R6/R7, byte-identical) ----------------
struct __align__(16) BS {
    float M[N_ * MSTRIDE];
    float r[RD];
    float key[RD];
    float add[RD];
    float wr[R_ * N_];
    float wu[N_];
    float wwsum[N_];
    float Ksm[R_ * N_];
    float m2[N_];
    float wlu[N_];
    float outh[NCLS];
    float key2[R_];
    float sig;
    float pad_[2];
};
#define BSF (sizeof(BS)/4)

#define OFF_SWRH   (2*BSF)
#define OFF_HPRE   (OFF_SWRH + 8000)
#define OFF_HT     (OFF_HPRE + 1600)
#define OFF_RALL   (OFF_HT   + 1600)
#define OFF_CSL    (OFF_RALL + 1312)
#define OFF_PBUF   (OFF_CSL  + 400)
#define SMEM_FLOATS (OFF_PBUF + 12800)

__device__ __forceinline__ float sigmoidf_(float x) { return 1.f / (1.f + expf(-x)); }

__global__ __launch_bounds__(THREADS) __cluster_dims__(CS, 1, 1)
void mann_recurrent(
    const float* __restrict__ bkey, const float* __restrict__ badd,
    const float* __restrict__ Wsig, const float* __restrict__ bsig,
    const float* __restrict__ Who,  const float* __restrict__ bho,
    const float* __restrict__ Wro,  const float* __restrict__ bro,
    const float* __restrict__ brh,  const float* __restrict__ bhh,
    float* __restrict__ out) {
    extern __shared__ float smemf[];
    BS* S          = reinterpret_cast<BS*>(smemf);
    float* sWrh    = smemf + OFF_SWRH;
    float* hpreAll = smemf + OFF_HPRE;
    float* htAll   = smemf + OFF_HT;
    float* rAll    = smemf + OFF_RALL;
    float* cSlice  = smemf + OFF_CSL;
    float* Pbuf    = smemf + OFF_PBUF;

    const int tid  = threadIdx.x;
    const int blk  = blockIdx.x;
    const int wid  = tid >> 5, lane = tid & 31;
    const unsigned rank = ctarank();
    const int bbase = (blk >> 2) * 8;

    for (int b = 0; b < BPB; b++) {
        BS& s = S[b];
        for (int i = tid; i < N_ * MSTRIDE; i += THREADS) s.M[i] = 0.f;
        for (int i = tid; i < RD; i += THREADS) s.r[i] = 0.f;
        for (int i = tid; i < R_ * N_; i += THREADS) s.wr[i] = 0.f;
        for (int i = tid; i < N_; i += THREADS) s.wu[i] = 0.f;
    }
    for (int i = tid; i < 8 * 200; i += THREADS) htAll[i] = 0.f;
    for (int i = tid; i < 8 * RSTR; i += THREADS) rAll[i] = 0.f;
    for (int i = tid; i < 8 * 50; i += THREADS) cSlice[i] = 0.f;
    for (int idx = tid; idx < 160 * 50; idx += THREADS) {
        int k = idx / 50, i = idx % 50;
        sWrh[idx] = g_WrhT[k * 200 + 50 * rank + i];
    }
    __syncthreads();
    CLUSTER_SYNC();

    const int p_b = tid & 7;
    const int p_i = tid >> 3;
    const int jg1 = 50 * rank + ((p_i < 50) ? p_i : 0);
    const float brh_r = brh[jg1];
    const int ci = tid % 50;
    const int cb = tid / 50;
    const int jg = 50 * rank + ci;
    float bh0 = bhh[jg], bh1 = bhh[200 + jg], bh2 = bhh[400 + jg], bh3 = bhh[600 + jg];
    const int fj = tid % 40;
    const int fb = tid / 40;
    const int jgka = 40 * rank + fj;
    const float bkey_r = bkey[jgka], badd_r = badd[jgka];

    for (int t = 0; t < T_; t++) {
        float G0 = 0.f, G1 = 0.f, G2 = 0.f, G3 = 0.f;
        if (tid < 400) {
            const float* Gp = g_G + ((size_t)(bbase + cb) * T_ + t) * G4H;
            G0 = Gp[jg]; G1 = Gp[200 + jg]; G2 = Gp[400 + jg]; G3 = Gp[600 + jg];
        }

        if (tid < 400) {
            const float* rr = &rAll[p_b * RSTR];
            float acc = htAll[p_b * 200 + jg1] + brh_r;
#pragma unroll 8
            for (int k = 0; k < RD; k++) acc += rr[k] * sWrh[k * 50 + p_i];
            bcast_all(&hpreAll[p_b * 200 + jg1], acc);
        } else if (wid == 13 || wid == 14) {
            int b = wid - 13;
            unsigned long long kv[4];
            float wl[4];
#pragma unroll
            for (int q = 0; q < 4; q++) {
                int n = lane + 32 * q;
                unsigned u = __float_as_uint(S[b].wu[n]);
                u = (u & 0x80000000u) ? ~u : (u | 0x80000000u);
                kv[q] = ((unsigned long long)u << 32) | (unsigned)n;
                wl[q] = 0.f;
            }
#pragma unroll
            for (int ss = 0; ss < 4; ss++) {
                unsigned long long m = kv[0]; int qi = 0;
#pragma unroll
                for (int q = 1; q < 4; q++) if (kv[q] < m) { m = kv[q]; qi = q; }
                unsigned long long wm = m;
#pragma unroll
                for (int o = 16; o > 0; o >>= 1) {
                    unsigned long long x = __shfl_xor_sync(0xffffffffu, wm, o);
                    if (x < wm) wm = x;
                }
                if (m == wm) { wl[qi] = 1.f; kv[qi] = ~0ull; }
            }
#pragma unroll
            for (int q = 0; q < 4; q++) S[b].wlu[lane + 32 * q] = wl[q];
        } else if (wid == 15 && t > 0) {
            for (int p = 0; p < BPB * NCLS; p++) {
                int b = p / NCLS, cls = p % NCLS;
                const float* rr = S[b].r;
                float acc = 0.f;
#pragma unroll
                for (int k = lane; k < RD; k += 32) acc += rr[k] * Wro[cls * RD + k];
#pragma unroll
                for (int o = 16; o > 0; o >>= 1) acc += __shfl_down_sync(0xffffffffu, acc, o);
                if (lane == 0)
                    out[((size_t)(blk * BPB + b) * T_ + (t - 1)) * NCLS + cls] = acc + S[b].outh[cls];
            }
        }
        CLUSTER_SYNC();

        if (tid < 400) {
            int i2 = tid % 50, ks = tid / 50;
            float ag[8][4];
#pragma unroll
            for (int b = 0; b < 8; b++)
#pragma unroll
                for (int g = 0; g < 4; g++) ag[b][g] = 0.f;
            const float4* W = reinterpret_cast<const float4*>(g_Wg4) + (50 * rank + i2);
            int k0 = 25 * ks;
#pragma unroll 5
            for (int kk = 0; kk < 25; kk++) {
                int k = k0 + kk;
                float4 w = W[k * 200];
#pragma unroll
                for (int b = 0; b < 8; b++) {
                    float hb = hpreAll[b * 200 + k];
                    ag[b][0] += w.x * hb; ag[b][1] += w.y * hb;
                    ag[b][2] += w.z * hb; ag[b][3] += w.w * hb;
                }
            }
#pragma unroll
            for (int b = 0; b < 8; b++)
#pragma unroll
                for (int g = 0; g < 4; g++)
                    Pbuf[(b * 4 + g) * 400 + ks * 50 + i2] = ag[b][g];
        }
        __syncthreads();

        if (tid < 400) {
            float s0 = G0 + bh0, s1 = G1 + bh1, s2 = G2 + bh2, s3 = G3 + bh3;
#pragma unroll
            for (int ks = 0; ks < 8; ks++) {
                s0 += Pbuf[(cb * 4 + 0) * 400 + ks * 50 + ci];
                s1 += Pbuf[(cb * 4 + 1) * 400 + ks * 50 + ci];
                s2 += Pbuf[(cb * 4 + 2) * 400 + ks * 50 + ci];
                s3 += Pbuf[(cb * 4 + 3) * 400 + ks * 50 + ci];
            }
            float ig = sigmoidf_(s0), fg = sigmoidf_(s1);
            float gg = tanhf(s2),    og = sigmoidf_(s3);
            float ct = fg * cSlice[cb * 50 + ci] + ig * gg;
            cSlice[cb * 50 + ci] = ct;
            float ht = og * tanhf(ct);
            bcast_all(&htAll[cb * 200 + jg], ht);
        }
        CLUSTER_SYNC();

        if (tid < 320) {
            int j = tid % 40, ks = tid / 40;
            float ak[8], aa[8];
#pragma unroll
            for (int b = 0; b < 8; b++) { ak[b] = 0.f; aa[b] = 0.f; }
            const float2* W = reinterpret_cast<const float2*>(g_Wka2) + (40 * rank + j);
            int k0 = 25 * ks;
#pragma unroll 5
            for (int kk = 0; kk < 25; kk++) {
                int k = k0 + kk;
                float2 w = W[k * 160];
#pragma unroll
                for (int b = 0; b < 8; b++) {
                    float hb = htAll[b * 200 + k];
                    ak[b] += w.x * hb; aa[b] += w.y * hb;
                }
            }
#pragma unroll
            for (int b = 0; b < 8; b++) {
                Pbuf[(b * 2 + 0) * 320 + ks * 40 + j] = ak[b];
                Pbuf[(b * 2 + 1) * 320 + ks * 40 + j] = aa[b];
            }
        } else if (wid == 10 || wid == 11) {
            int b = wid - 10;
            const float* hh = &htAll[(rank * 2 + b) * 200];
            float p = 0.f;
            for (int k = lane; k < H_; k += 32) p += hh[k] * Wsig[k];
#pragma unroll
            for (int o = 16; o > 0; o >>= 1) p += __shfl_xor_sync(0xffffffffu, p, o);
            if (lane == 0) S[b].sig = p + bsig[0];
        } else if (wid == 12 || wid == 13) {
            int b = wid - 12;
            const float* hh = &htAll[(rank * 2 + b) * 200];
            for (int cls = 0; cls < NCLS; cls++) {
                float acc = 0.f;
#pragma unroll
                for (int k = lane; k < H_; k += 32) acc += hh[k] * Who[cls * H_ + k];
#pragma unroll
                for (int o = 16; o > 0; o >>= 1) acc += __shfl_down_sync(0xffffffffu, acc, o);
                if (lane == 0) S[b].outh[cls] = acc + bho[cls] + bro[cls];
            }
        }
        __syncthreads();

        if (tid < 320) {
            float vk = bkey_r, va = badd_r;
#pragma unroll
            for (int ks = 0; ks < 8; ks++) {
                vk += Pbuf[(fb * 2 + 0) * 320 + ks * 40 + fj];
                va += Pbuf[(fb * 2 + 1) * 320 + ks * 40 + fj];
            }
            int owner = fb >> 1, lb = fb & 1;
            st_rank(&S[lb].key[jgka], vk, owner);
            st_rank(&S[lb].add[jgka], va, owner);
        }
        CLUSTER_SYNC();

        {
            int b = tid >> 8;
            int n = (tid >> 1) & 127;
            int dh = tid & 1;
            BS& s = S[b];
            float sg = s.sig, omsg = 1.f - sg;
            float wl = s.wlu[n];
            float w0 = sg * s.wr[n]       + omsg * wl;
            float w1 = sg * s.wr[128 + n] + omsg * wl;
            float w2 = sg * s.wr[256 + n] + omsg * wl;
            float w3 = sg * s.wr[384 + n] + omsg * wl;
            if (dh == 0) s.wwsum[n] = w0 + w1 + w2 + w3;
            float m2p = 0.f;
            int d0 = dh * 20;
#pragma unroll
            for (int dd = 0; dd < 20; dd++) {
                int d = d0 + dd;
                float mv = s.M[n * MSTRIDE + d] * wl
                         + w0 * s.add[d] + w1 * s.add[40 + d]
                         + w2 * s.add[80 + d] + w3 * s.add[120 + d];
                s.M[n * MSTRIDE + d] = mv;
                m2p += mv * mv;
            }
            m2p += __shfl_xor_sync(0xffffffffu, m2p, 1);
            if (dh == 0) s.m2[n] = m2p;
        }
        if (tid < 8) {
            int b = tid >> 2, r = tid & 3;
            float sum = 0.f;
#pragma unroll
            for (int d = 0; d < D_; d++) { float v = S[b].key[r * 40 + d]; sum += v * v; }
            S[b].key2[r] = sum;
        }
        __syncthreads();

        for (int e = tid; e < 1024; e += THREADS) {
            int b = e >> 9, rn = e & 511, r = rn >> 7, n = rn & 127;
            BS& s = S[b];
            const float* kp = s.key + r * 40;
            const float* mp = s.M + n * MSTRIDE;
            float dot = 0.f;
#pragma unroll
            for (int d = 0; d < D_; d++) dot += kp[d] * mp[d];
            s.Ksm[rn] = dot / sqrtf(s.key2[r] * s.m2[n] + 1e-6f);
        }
        __syncthreads();

        if (wid < 8) {
            int b = wid >> 2, r = wid & 3;
            BS& s = S[b];
            float v0 = s.Ksm[r * N_ + lane];
            float v1 = s.Ksm[r * N_ + 32 + lane];
            float v2 = s.Ksm[r * N_ + 64 + lane];
            float v3 = s.Ksm[r * N_ + 96 + lane];
            float mx = fmaxf(fmaxf(v0, v1), fmaxf(v2, v3));
#pragma unroll
            for (int o = 16; o > 0; o >>= 1) mx = fmaxf(mx, __shfl_xor_sync(0xffffffffu, mx, o));
            float e0 = expf(v0 - mx), e1 = expf(v1 - mx), e2 = expf(v2 - mx), e3 = expf(v3 - mx);
            float su = e0 + e1 + e2 + e3;
#pragma unroll
            for (int o = 16; o > 0; o >>= 1) su += __shfl_xor_sync(0xffffffffu, su, o);
            float inv = 1.f / su;
            s.wr[r * N_ + lane]      = e0 * inv;
            s.wr[r * N_ + 32 + lane] = e1 * inv;
            s.wr[r * N_ + 64 + lane] = e2 * inv;
            s.wr[r * N_ + 96 + lane] = e3 * inv;
        }
        __syncthreads();

        if (tid < 256) {
            int b = tid >> 7, n = tid & 127;
            BS& s = S[b];
            s.wu[n] = 0.95f * s.wu[n]
                    + (s.wr[n] + s.wr[128 + n] + s.wr[256 + n] + s.wr[384 + n])
                    + s.wwsum[n];
        }
        if (tid < 320) {
            int b = tid / 160, rd = tid % 160;
            int r = rd / 40, d = rd % 40;
            BS& s = S[b];
            const float* wrp = s.wr + r * N_;
            float dot = 0.f;
#pragma unroll 8
            for (int n = 0; n < N_; n++) dot += wrp[n] * s.M[n * MSTRIDE + d];
            s.r[rd] = dot;
            bcast_all(&rAll[(rank * 2 + b) * RSTR + rd], dot);
        }
        CLUSTER_SYNC();
    }

    if (wid == 15) {
        for (int p = 0; p < BPB * NCLS; p++) {
            int b = p / NCLS, cls = p % NCLS;
            const float* rr = S[b].r;
            float acc = 0.f;
#pragma unroll
            for (int k = lane; k < RD; k += 32) acc += rr[k] * Wro[cls * RD + k];
#pragma unroll
            for (int o = 16; o > 0; o >>= 1) acc += __shfl_down_sync(0xffffffffu, acc, o);
            if (lane == 0)
                out[((size_t)(blk * BPB + b) * T_ + (T_ - 1)) * NCLS + cls] = acc + S[b].outh[cls];
        }
    }
}

// ---------------- launch ----------------
extern "C" void kernel_launch(void* const* d_in, const int* in_sizes, int n_in,
                              void* d_out, int out_size) {
    const float* x    = (const float*)d_in[0];
    const float* Wkey = (const float*)d_in[1];
    const float* bkey = (const float*)d_in[2];
    const float* Wadd = (const float*)d_in[3];
    const float* badd = (const float*)d_in[4];
    const float* Wsig = (const float*)d_in[5];
    const float* bsig = (const float*)d_in[6];
    const float* Who  = (const float*)d_in[7];
    const float* bho  = (const float*)d_in[8];
    const float* Wro  = (const float*)d_in[9];
    const float* bro  = (const float*)d_in[10];
    const float* Wrh  = (const float*)d_in[11];
    const float* brh  = (const float*)d_in[12];
    const float* Wih  = (const float*)d_in[13];
    const float* bih  = (const float*)d_in[14];
    const float* Whh  = (const float*)d_in[15];
    const float* bhh  = (const float*)d_in[16];
    float* out = (float*)d_out;

    prep_weights<<<1000, 256>>>(Whh, Wkey, Wadd, Wrh);
    gemm_gates_x<<<dim3((G4H + GTN - 1) / GTN, B_ * T_ / GTM), 256>>>(x, Wih, bih);

    size_t shmem = (size_t)SMEM_FLOATS * 4;
    cudaFuncSetAttribute(mann_recurrent, cudaFuncAttributeMaxDynamicSharedMemorySize, (int)shmem);
    mann_recurrent<<<NBLK, THREADS, shmem>>>(bkey, badd, Wsig, bsig, Who, bho,
                                             Wro, bro, brh, bhh, out);
}